// round 12
// baseline (speedup 1.0000x reference)
#include <cuda_runtime.h>

// Problem constants (fixed by the reference)
#define B       32
#define N       2048
#define OUTD    100
#define JSPLITS 16
#define JCHUNK  (N / JSPLITS)        // 128
#define BPG     4                    // batch rows per block (W register reuse)
#define BGROUPS (B / BPG)            // 8
#define GRID    (JSPLITS * BGROUPS)  // 128 blocks
#define NT      512
#define NW      16
#define J_PER_WARP (JCHUNK / NW)     // 8

// out[b,o] = sum_j rem[b,j] * W[j,o]
// rem[b,j] = (q[b,j] - float(N*c[b,j] + S_b))^2, c = (int)q, S_b = sum_j c[b,j]
// Exact vs reference: all integer partials < 2^24, so the reference's fp32
// reduce of the [N,N] broadcast equals the int32 closed form bit-for-bit.
//
// Tail (single graph node): splits RED.ADD.F32 into a persistent g_acc
// (zeroed at module load); the 16th-arriving block per batch-group copies the
// accumulated values to out and re-zeros g_acc for the next replay. Same
// output on every launch (up to ~1e-7 FP reassociation of the 16 split adds).

__device__ float        g_acc[B][OUTD];          // zero-initialized at load
__device__ unsigned int g_count[BGROUPS];        // zero-initialized

__global__ __launch_bounds__(NT, 1)
void fused_rowstat_gemv_kernel(const float* __restrict__ q,
                               const float* __restrict__ W,
                               float* __restrict__ out)
{
    __shared__ float4 rem4[BPG][JCHUNK / 4];     // 2 KB
    __shared__ float  part_sh[NW][BPG * OUTD];   // 25.6 KB
    __shared__ int    qsum[NW];
    __shared__ int    last_flag;

    const int tid  = threadIdx.x;
    const int wid  = tid >> 5;
    const int lane = tid & 31;
    const int s    = blockIdx.x & (JSPLITS - 1);   // j-split index
    const int bg   = blockIdx.x >> 4;              // batch-group index
    const int j0   = s * JCHUNK;

    // ---- Prefetch W into registers (block-index-dependent only). Eight
    //      independent, fully-coalesced LDG.128 retire behind phase 1. ----
    const int g  = lane;                 // output group: o = 4g..4g+3 (g<25)
    const int jw = wid * J_PER_WARP;
    float4 w4[J_PER_WARP];
    if (g < 25) {
        const float* Wg = W + (size_t)(j0 + jw) * OUTD + g * 4;
        #pragma unroll
        for (int jj = 0; jj < J_PER_WARP; ++jj)
            w4[jj] = *reinterpret_cast<const float4*>(Wg + jj * OUTD);
    }

    // ---- Phase 1: int row-sums for the 4 rows (4 warps per row); keep the
    //      float4 that belongs to this block's j-chunk in a register. ----
    const int r       = wid >> 2;                  // row within group
    const int quarter = wid & 3;
    const int i_need  = s >> 2;                    // unroll step holding chunk s
    const bool owns_chunk = (quarter == (s & 3));
    float4 vkeep;
    {
        const float4* q4 = reinterpret_cast<const float4*>(q + (bg * BPG + r) * N);
        const int t = quarter * 32 + lane;         // 0..127
        int ss = 0;
        #pragma unroll
        for (int i = 0; i < 4; ++i) {
            float4 v = q4[t + 128 * i];
            ss += (int)v.x + (int)v.y + (int)v.z + (int)v.w;
            if (i == i_need) vkeep = v;
        }
        ss = __reduce_add_sync(0xFFFFFFFFu, ss);   // REDUX.SUM
        if (lane == 0) qsum[wid] = ss;
    }
    __syncthreads();

    // ---- Phase 2: rem chunk straight from registers; owner warps read the
    //      four per-warp sums via broadcast LDS (no extra barrier round). ----
    if (owns_chunk) {
        const int   S = qsum[4*r] + qsum[4*r+1] + qsum[4*r+2] + qsum[4*r+3];
        const float4 v = vkeep;
        int   c0 = (int)v.x, c1 = (int)v.y, c2 = (int)v.z, c3 = (int)v.w;
        float d0 = v.x - (float)(N * c0 + S);
        float d1 = v.y - (float)(N * c1 + S);
        float d2 = v.z - (float)(N * c2 + S);
        float d3 = v.w - (float)(N * c3 + S);
        rem4[r][lane] = make_float4(d0*d0, d1*d1, d2*d2, d3*d3);
    }
    __syncthreads();

    // ---- Phase 3: GEMV on registers + smem broadcast (measured-best form) ----
    if (g < 25) {
        const float* rem = reinterpret_cast<const float*>(&rem4[0][0]);
        float acc[BPG][4];
        #pragma unroll
        for (int rr = 0; rr < BPG; ++rr)
            acc[rr][0] = acc[rr][1] = acc[rr][2] = acc[rr][3] = 0.f;
        #pragma unroll
        for (int jj = 0; jj < J_PER_WARP; ++jj) {
            #pragma unroll
            for (int rr = 0; rr < BPG; ++rr) {
                float rv = rem[rr * JCHUNK + jw + jj];
                acc[rr][0] = fmaf(rv, w4[jj].x, acc[rr][0]);
                acc[rr][1] = fmaf(rv, w4[jj].y, acc[rr][1]);
                acc[rr][2] = fmaf(rv, w4[jj].z, acc[rr][2]);
                acc[rr][3] = fmaf(rv, w4[jj].w, acc[rr][3]);
            }
        }
        #pragma unroll
        for (int rr = 0; rr < BPG; ++rr)
            *reinterpret_cast<float4*>(&part_sh[wid][rr * OUTD + g * 4]) =
                make_float4(acc[rr][0], acc[rr][1], acc[rr][2], acc[rr][3]);
    }
    __syncthreads();

    // ---- Phase 4: reduce 16 warps, RED split partial into g_acc ----
    if (tid < BPG * OUTD) {                        // 400 of 512 threads
        float ssum = 0.f;
        #pragma unroll
        for (int w = 0; w < NW; ++w) ssum += part_sh[w][tid];
        const int rr = tid / OUTD;
        const int o  = tid - rr * OUTD;
        atomicAdd(&g_acc[bg * BPG + rr][o], ssum); // RED.ADD.F32, no return
        __threadfence();                           // order RED before release
    }
    __syncthreads();

    // ---- Phase 5: 16th arrival per bgroup copies g_acc -> out, re-zeros ----
    if (tid == 0) {
        unsigned old;
        asm volatile("atom.add.acq_rel.gpu.global.u32 %0, [%1], %2;"
                     : "=r"(old) : "l"(&g_count[bg]), "r"(1u) : "memory");
        last_flag = (old == JSPLITS - 1);
        if (last_flag) g_count[bg] = 0;            // self-reset for graph replay
    }
    __syncthreads();

    if (last_flag && tid < BPG * OUTD) {
        const int rr = tid / OUTD;
        const int o  = tid - rr * OUTD;
        const int b  = bg * BPG + rr;
        float v = __ldcg(&g_acc[b][o]);            // L1-bypassing load
        out[b * OUTD + o] = v;
        g_acc[b][o] = 0.f;                         // ready for next replay
    }
}

extern "C" void kernel_launch(void* const* d_in, const int* in_sizes, int n_in,
                              void* d_out, int out_size)
{
    const float* q = (const float*)d_in[0];   // [32, 2048] f32
    const float* W = (const float*)d_in[1];   // [2048, 100] f32
    float* out = (float*)d_out;               // [32, 100] f32
    (void)in_sizes; (void)n_in; (void)out_size;

    fused_rowstat_gemv_kernel<<<GRID, NT>>>(q, W, out);
}

// round 13
// speedup vs baseline: 1.0036x; 1.0036x over previous
#include <cuda_runtime.h>

// Problem constants (fixed by the reference)
#define B       32
#define N       2048
#define OUTD    100
#define JSPLITS 16
#define JCHUNK  (N / JSPLITS)        // 128
#define BPG     4                    // batch rows per block (W register reuse)
#define BGROUPS (B / BPG)            // 8
#define NWORK   (JSPLITS * BGROUPS)  // 128 worker blocks
#define GRID    (NWORK + 1)          // + 1 zeroer block
#define NT      512
#define NW      16
#define J_PER_WARP (JCHUNK / NW)     // 8

// out[b,o] = sum_j rem[b,j] * W[j,o]
// rem[b,j] = (q[b,j] - float(N*c[b,j] + S_b))^2, c = (int)q, S_b = sum_j c[b,j]
// Exact vs reference: all integer partials < 2^24, so the reference's fp32
// reduce of the [N,N] broadcast equals the int32 closed form bit-for-bit.
//
// Single graph node. Block 128 zeroes out and release-publishes g_ready.
// Worker blocks compute their split partial (fixed-order), acquire-spin on
// g_ready (already set by the time they arrive), then fire-and-forget
// RED.ADD.F32 into out. The 128th worker past the spin resets the flags,
// restoring initial state for the next graph replay (no call-count state;
// same work and same output every call, up to ~1e-7 RED reassociation).

__device__ unsigned int g_ready;     // zero-initialized
__device__ unsigned int g_done;      // zero-initialized

__global__ __launch_bounds__(NT, 1)
void fused_rowstat_gemv_kernel(const float* __restrict__ q,
                               const float* __restrict__ W,
                               float* __restrict__ out)
{
    // ---- Zeroer block: clear out, then release-publish readiness ----
    if (blockIdx.x == NWORK) {
        const int tid = threadIdx.x;
        float2* o2 = reinterpret_cast<float2*>(out);      // 1600 float2
        #pragma unroll
        for (int i = tid; i < (B * OUTD) / 2; i += NT)
            o2[i] = make_float2(0.f, 0.f);
        __syncthreads();                                  // all stores issued
        if (tid == 0)
            asm volatile("st.release.gpu.global.u32 [%0], %1;"
                         :: "l"(&g_ready), "r"(1u) : "memory");
        return;
    }

    __shared__ float4 rem4[BPG][JCHUNK / 4];     // 2 KB
    __shared__ float  part_sh[NW][BPG * OUTD];   // 25.6 KB
    __shared__ int    qsum[NW];

    const int tid  = threadIdx.x;
    const int wid  = tid >> 5;
    const int lane = tid & 31;
    const int s    = blockIdx.x & (JSPLITS - 1);   // j-split index
    const int bg   = blockIdx.x >> 4;              // batch-group index
    const int j0   = s * JCHUNK;

    // ---- Prefetch W into registers (block-index-dependent only). Eight
    //      independent, fully-coalesced LDG.128 retire behind phase 1. ----
    const int g  = lane;                 // output group: o = 4g..4g+3 (g<25)
    const int jw = wid * J_PER_WARP;
    float4 w4[J_PER_WARP];
    if (g < 25) {
        const float* Wg = W + (size_t)(j0 + jw) * OUTD + g * 4;
        #pragma unroll
        for (int jj = 0; jj < J_PER_WARP; ++jj)
            w4[jj] = *reinterpret_cast<const float4*>(Wg + jj * OUTD);
    }

    // ---- Phase 1: int row-sums for the 4 rows (4 warps per row); keep the
    //      float4 that belongs to this block's j-chunk in a register. ----
    const int r       = wid >> 2;                  // row within group
    const int quarter = wid & 3;
    const int i_need  = s >> 2;                    // unroll step holding chunk s
    const bool owns_chunk = (quarter == (s & 3));
    float4 vkeep;
    {
        const float4* q4 = reinterpret_cast<const float4*>(q + (bg * BPG + r) * N);
        const int t = quarter * 32 + lane;         // 0..127
        int ss = 0;
        #pragma unroll
        for (int i = 0; i < 4; ++i) {
            float4 v = q4[t + 128 * i];
            ss += (int)v.x + (int)v.y + (int)v.z + (int)v.w;
            if (i == i_need) vkeep = v;
        }
        ss = __reduce_add_sync(0xFFFFFFFFu, ss);   // REDUX.SUM
        if (lane == 0) qsum[wid] = ss;
    }
    __syncthreads();

    // ---- Phase 2: rem chunk straight from registers; owner warps read the
    //      four per-warp sums via broadcast LDS (no extra barrier round). ----
    if (owns_chunk) {
        const int   S = qsum[4*r] + qsum[4*r+1] + qsum[4*r+2] + qsum[4*r+3];
        const float4 v = vkeep;
        int   c0 = (int)v.x, c1 = (int)v.y, c2 = (int)v.z, c3 = (int)v.w;
        float d0 = v.x - (float)(N * c0 + S);
        float d1 = v.y - (float)(N * c1 + S);
        float d2 = v.z - (float)(N * c2 + S);
        float d3 = v.w - (float)(N * c3 + S);
        rem4[r][lane] = make_float4(d0*d0, d1*d1, d2*d2, d3*d3);
    }
    __syncthreads();

    // ---- Phase 3: GEMV on registers + smem broadcast (measured-best form) ----
    if (g < 25) {
        const float* rem = reinterpret_cast<const float*>(&rem4[0][0]);
        float acc[BPG][4];
        #pragma unroll
        for (int rr = 0; rr < BPG; ++rr)
            acc[rr][0] = acc[rr][1] = acc[rr][2] = acc[rr][3] = 0.f;
        #pragma unroll
        for (int jj = 0; jj < J_PER_WARP; ++jj) {
            #pragma unroll
            for (int rr = 0; rr < BPG; ++rr) {
                float rv = rem[rr * JCHUNK + jw + jj];
                acc[rr][0] = fmaf(rv, w4[jj].x, acc[rr][0]);
                acc[rr][1] = fmaf(rv, w4[jj].y, acc[rr][1]);
                acc[rr][2] = fmaf(rv, w4[jj].z, acc[rr][2]);
                acc[rr][3] = fmaf(rv, w4[jj].w, acc[rr][3]);
            }
        }
        #pragma unroll
        for (int rr = 0; rr < BPG; ++rr)
            *reinterpret_cast<float4*>(&part_sh[wid][rr * OUTD + g * 4]) =
                make_float4(acc[rr][0], acc[rr][1], acc[rr][2], acc[rr][3]);
    }
    __syncthreads();

    // ---- Phase 4: reduce 16 warps; wait for the zeroer (normally already
    //      done -> single L2 broadcast load); RED into out. ----
    if (tid < BPG * OUTD) {                        // 400 of 512 threads
        float ssum = 0.f;
        #pragma unroll
        for (int w = 0; w < NW; ++w) ssum += part_sh[w][tid];

        unsigned rdy;
        do {
            asm volatile("ld.acquire.gpu.global.u32 %0, [%1];"
                         : "=r"(rdy) : "l"(&g_ready) : "memory");
        } while (rdy == 0);

        const int rr = tid / OUTD;
        const int o  = tid - rr * OUTD;
        atomicAdd(&out[(bg * BPG + rr) * OUTD + o], ssum);  // RED.ADD.F32
    }
    __syncthreads();   // all 400 threads passed the spin before tid0 counts

    // ---- Replay-state reset: 128th block past the spin restores flags ----
    if (tid == 0) {
        unsigned old = atomicAdd(&g_done, 1u);
        if (old == NWORK - 1) {       // every worker already passed the spin
            g_done  = 0u;
            g_ready = 0u;             // visible to next replay via node boundary
        }
    }
}

extern "C" void kernel_launch(void* const* d_in, const int* in_sizes, int n_in,
                              void* d_out, int out_size)
{
    const float* q = (const float*)d_in[0];   // [32, 2048] f32
    const float* W = (const float*)d_in[1];   // [2048, 100] f32
    float* out = (float*)d_out;               // [32, 100] f32
    (void)in_sizes; (void)n_in; (void)out_size;

    fused_rowstat_gemv_kernel<<<GRID, NT>>>(q, W, out);
}